// round 6
// baseline (speedup 1.0000x reference)
#include <cuda_runtime.h>
#include <stdint.h>
#include <math.h>

#define T_LEN 8192
#define B_CNT 16
#define NSTEP 8189            // T-3 markov samples
#define SEG_N 64
#define SEG_L 128             // SEG_N*SEG_L = 8192 (pad last 3 steps)
#define SMP_STRIDE 8208       // 16-byte lead pad + 8192

// ---------------- device scratch (no allocations allowed) ----------------
__device__ uint8_t g_snsp[B_CNT * T_LEN];        // per (b,t): sn | sp<<2
__device__ uint8_t g_smp[B_CNT * SMP_STRIDE];    // [16B pad][8192 samples] per b

// ---------------- threefry-2x32 (20 rounds), matches JAX exactly ----------------
__device__ __forceinline__ void tf2x32(uint32_t k0, uint32_t k1,
                                       uint32_t x0, uint32_t x1,
                                       uint32_t& o0, uint32_t& o1) {
    uint32_t ks2 = k0 ^ k1 ^ 0x1BD11BDAu;
    x0 += k0; x1 += k1;
#define RND(r) { x0 += x1; x1 = __funnelshift_l(x1, x1, (r)); x1 ^= x0; }
    RND(13) RND(15) RND(26) RND(6)
    x0 += k1; x1 += ks2 + 1u;
    RND(17) RND(29) RND(16) RND(24)
    x0 += ks2; x1 += k0 + 2u;
    RND(13) RND(15) RND(26) RND(6)
    x0 += k0; x1 += k1 + 3u;
    RND(17) RND(29) RND(16) RND(24)
    x0 += k1; x1 += ks2 + 4u;
    RND(13) RND(15) RND(26) RND(6)
    x0 += ks2; x1 += k0 + 5u;
#undef RND
    o0 = x0; o1 = x1;
}

// JAX uniform(minval=tiny, maxval=1) from raw bits
__device__ __forceinline__ float u_from_bits(uint32_t bits) {
    const float tiny = 1.1754943508222875e-38f;  // FLT_MIN
    float f = __uint_as_float((bits >> 9) | 0x3f800000u) - 1.0f;
    return fmaxf(tiny, f + tiny);
}

__device__ __forceinline__ float gum_fast(uint32_t bits) {
    float u = u_from_bits(bits);
    return -logf(-logf(u));
}

// correctly-rounded f32 gumbel via double logs (only when argmax margin is tight)
__device__ __noinline__ float gum_precise(uint32_t bits) {
    float u = u_from_bits(bits);
    float inner = (float)log((double)u);
    return -(float)log((double)(-inner));
}

// ---------------- K1: per-(t,b) candidate samples sn / sp ----------------
// Fully independent threads: per-thread key tf + 3 bit tf (ILP 4), no smem/syncs.
__global__ void __launch_bounds__(256) k1_gen(const int* __restrict__ seed_ptr) {
    int tid = blockIdx.x * blockDim.x + threadIdx.x;   // 131072 threads
    int t = tid & (T_LEN - 1);
    int b = tid >> 13;

    if (t >= NSTEP) {     // pad steps 8189..8191 (never affect the output)
        g_snsp[b * T_LEN + t] = (uint8_t)(1u | (1u << 2));
        return;
    }

    uint32_t kt0, kt1;
    tf2x32(0u, (uint32_t)(*seed_ptr), 0u, (uint32_t)t, kt0, kt1);  // keys[t]

    uint32_t bt[3];
#pragma unroll
    for (int k = 0; k < 3; k++) {   // bits[(16,3)][3b+k] = o0^o1 of tf(key_t, 0, j)
        uint32_t o0, o1;
        tf2x32(kt0, kt1, 0u, (uint32_t)(3 * b + k), o0, o1);
        bt[k] = o0 ^ o1;
    }

    // logits as exact-to-f32 precomputed literals:
    //   lp  = ln(f32(0.1)), ls = ln(f32(0.8)),
    //   l21 = ln(f32(8/9)-ish), l22 = ln(f32(1/9)-ish)  (special renormalized row)
    const float lp  = (float)-2.3025850780928845;
    const float ls  = (float)-0.22314353641304875;
    const float l21 = (float)-0.11778302820580285;
    const float l22 = (float)-2.19722456988563878;

    float g0 = gum_fast(bt[0]), g1 = gum_fast(bt[1]), g2 = gum_fast(bt[2]);
    float v0 = lp + g0, v1 = ls + g1, v2 = lp + g2;
    float w1 = l21 + g1, w2 = l22 + g2;

    float mmin = fminf(fminf(fabsf(v0 - v1), fabsf(v0 - v2)),
                       fminf(fabsf(v1 - v2), fabsf(w1 - w2)));
    if (mmin < 1e-3f) {   // tight argmax margin: redo exactly (DP logs, rare path)
        double p = 0.1, s = 1.0 - 2.0 * 0.1;
        float flp  = (float)log((double)(float)p);
        float fls  = (float)log((double)(float)s);
        float fl21 = (float)log((double)(float)(s / (p + s)));
        float fl22 = (float)log((double)(float)(p / (p + s)));
        g0 = gum_precise(bt[0]); g1 = gum_precise(bt[1]); g2 = gum_precise(bt[2]);
        v0 = flp + g0; v1 = fls + g1; v2 = flp + g2;
        w1 = fl21 + g1; w2 = fl22 + g2;
    }

    int sn = 0; float best = v0;              // jnp.argmax first-max semantics
    if (v1 > best) { best = v1; sn = 1; }
    if (v2 > best) { sn = 2; }
    int sp = (w1 >= w2) ? 1 : 2;              // special row [-inf, w1, w2]

    g_snsp[b * T_LEN + t] = (uint8_t)(sn | (sp << 2));
}

// compose two 9-state maps packed as nibbles: (f ∘ g)(i) = f[g[i]]
__device__ __forceinline__ unsigned long long map_comp(unsigned long long f,
                                                       unsigned long long g) {
    unsigned long long r = 0ull;
#pragma unroll
    for (int i = 0; i < 9; i++) {
        uint32_t gi = (uint32_t)(g >> (4 * i)) & 15u;
        uint32_t fi = (uint32_t)(f >> (4 * gi)) & 15u;
        r |= (unsigned long long)fi << (4 * i);
    }
    return r;
}

// ---------------- K2: fused speculative chain (one block per batch) ----------------
__global__ void __launch_bounds__(576) k2_chain() {
    __shared__ uint8_t s_end[SEG_N][9];
    __shared__ unsigned long long s_map[SEG_N];
    int b = blockIdx.x;
    int tid = threadIdx.x;

    {   // ---- phase A: 64 segs x 9 speculative start states ----
        int seg = tid / 9, s0 = tid % 9;
        const uint4* src = (const uint4*)(g_snsp + b * T_LEN + seg * SEG_L);
        uint4 w[8];
#pragma unroll
        for (int q = 0; q < 8; q++) w[q] = __ldg(&src[q]);   // MLP=8 up front
        uint32_t cc = (((uint32_t)(s0 / 3)) << 2) | (uint32_t)(s0 % 3);
#pragma unroll
        for (int q = 0; q < 8; q++) {
            uint32_t ws[4] = {w[q].x, w[q].y, w[q].z, w[q].w};
#pragma unroll
            for (int wi = 0; wi < 4; wi++) {
                uint32_t word = ws[wi];
#pragma unroll
                for (int bi = 0; bi < 4; bi++) {
                    uint32_t byte = word >> (8 * bi);
                    uint32_t s = (cc == 9u) ? ((byte >> 2) & 3u) : (byte & 3u);
                    cc = (s << 2) | (cc >> 2);
                }
            }
        }
        s_end[seg][s0] = (uint8_t)((cc >> 2) * 3u + (cc & 3u));
    }
    __syncthreads();

    if (tid < SEG_N) {    // pack 9 end states into one nibble map
        unsigned long long m = 0ull;
#pragma unroll
        for (int i = 0; i < 9; i++)
            m |= (unsigned long long)s_end[tid][i] << (4 * i);
        s_map[tid] = m;
    }
    __syncthreads();

    // ---- phase B: Kogge-Stone inclusive prefix s_map[i] = m_i ∘ ... ∘ m_0 ----
#pragma unroll
    for (int d = 1; d < SEG_N; d <<= 1) {
        unsigned long long v;
        if (tid < SEG_N) {
            v = s_map[tid];
            if (tid >= d) v = map_comp(v, s_map[tid - d]);
        }
        __syncthreads();
        if (tid < SEG_N) s_map[tid] = v;
        __syncthreads();
    }

    if (tid == 0) g_smp[b * SMP_STRIDE + 15] = 1;   // pad byte: m(to=0) = 1

    if (tid < SEG_N) {    // ---- phase C: replay with true start ----
        int seg = tid;
        int i0 = (seg == 0) ? 4 : (int)((s_map[seg - 1] >> 16) & 15ull);
        const uint4* src = (const uint4*)(g_snsp + b * T_LEN + seg * SEG_L);
        uint4 w[8];
#pragma unroll
        for (int q = 0; q < 8; q++) w[q] = __ldg(&src[q]);
        uint32_t cc = (((uint32_t)(i0 / 3)) << 2) | (uint32_t)(i0 % 3);
        uint4* dst = (uint4*)(g_smp + b * SMP_STRIDE + 16 + seg * SEG_L);
#pragma unroll
        for (int q = 0; q < 8; q++) {
            uint32_t in[4] = {w[q].x, w[q].y, w[q].z, w[q].w};
            uint32_t out[4];
#pragma unroll
            for (int wi = 0; wi < 4; wi++) {
                uint32_t word = in[wi], ow = 0u;
#pragma unroll
                for (int bi = 0; bi < 4; bi++) {
                    uint32_t s = (cc == 9u) ? ((word >> (8 * bi + 2)) & 3u)
                                            : ((word >> (8 * bi)) & 3u);
                    cc = (s << 2) | (cc >> 2);
                    ow |= s << (8 * bi);
                }
                out[wi] = ow;
            }
            dst[q] = make_uint4(out[0], out[1], out[2], out[3]);
        }
    }
}

// ---------------- K4: vectorized gather (16 outputs / thread) ----------------------
// out[bi, to] = x[bi, to + m(b,to)];  m bytes live at g_smp[b*STRIDE + 15 + to]
__global__ void __launch_bounds__(256) k4_gather(const float* __restrict__ x,
                                                 float* __restrict__ out) {
    int t16 = blockIdx.x * blockDim.x + threadIdx.x;  // outputs 16*t16 .. +15
    int bi = blockIdx.y;                              // b*256 + i
    int b = bi >> 8;

    // m bytes j=0..15 at byte pos 16t16+15..+30 -> two aligned uint4 index loads
    const uint4* mwv = (const uint4*)(g_smp + b * SMP_STRIDE);
    uint4 W0 = __ldg(&mwv[t16]);          // bytes 16t16 .. +15
    uint4 W1 = __ldg(&mwv[t16 + 1]);      // bytes 16t16+16 .. +31
    uint32_t mwd[4];
    mwd[0] = __funnelshift_r(W0.w, W1.x, 24);   // m for j=0..3
    mwd[1] = __funnelshift_r(W1.x, W1.y, 24);   // j=4..7
    mwd[2] = __funnelshift_r(W1.y, W1.z, 24);   // j=8..11
    mwd[3] = __funnelshift_r(W1.z, W1.w, 24);   // j=12..15

    const float* xr = x + (size_t)bi * 8192 + 16 * t16;
    float xv[18];
    {
        float4 A = *(const float4*)xr;
        float4 Bv = *(const float4*)(xr + 4);
        float4 C = *(const float4*)(xr + 8);
        float4 D = *(const float4*)(xr + 12);
        xv[0]=A.x; xv[1]=A.y; xv[2]=A.z; xv[3]=A.w;
        xv[4]=Bv.x; xv[5]=Bv.y; xv[6]=Bv.z; xv[7]=Bv.w;
        xv[8]=C.x; xv[9]=C.y; xv[10]=C.z; xv[11]=C.w;
        xv[12]=D.x; xv[13]=D.y; xv[14]=D.z; xv[15]=D.w;
    }
    bool full = (t16 < 511);              // last thread: only 14 outputs (8190 = 16*511+14)
    xv[16] = 0.f; xv[17] = 0.f;
    if (full) { float2 e = *(const float2*)(xr + 16); xv[16] = e.x; xv[17] = e.y; }

    float o[16];
#pragma unroll
    for (int j = 0; j < 16; j++) {
        uint32_t m = (mwd[j >> 2] >> (8 * (j & 3))) & 3u;
        o[j] = (m == 0u) ? xv[j] : ((m == 1u) ? xv[j + 1] : xv[j + 2]);
    }

    float* orow = out + (size_t)bi * 8190 + 16 * t16;
    bool al16 = ((bi & 1) == 0);          // even rows: 16B-aligned stores
    if (full) {
        if (al16) {
#pragma unroll
            for (int q = 0; q < 4; q++)
                *(float4*)(orow + 4 * q) = make_float4(o[4*q], o[4*q+1], o[4*q+2], o[4*q+3]);
        } else {
#pragma unroll
            for (int q = 0; q < 8; q++)
                *(float2*)(orow + 2 * q) = make_float2(o[2*q], o[2*q+1]);
        }
    } else {                              // 14 outputs
        if (al16) {
#pragma unroll
            for (int q = 0; q < 3; q++)
                *(float4*)(orow + 4 * q) = make_float4(o[4*q], o[4*q+1], o[4*q+2], o[4*q+3]);
            *(float2*)(orow + 12) = make_float2(o[12], o[13]);
        } else {
#pragma unroll
            for (int q = 0; q < 7; q++)
                *(float2*)(orow + 2 * q) = make_float2(o[2*q], o[2*q+1]);
        }
    }
}

extern "C" void kernel_launch(void* const* d_in, const int* in_sizes, int n_in,
                              void* d_out, int out_size) {
    const float* x = (const float*)d_in[0];
    const int* seed = (const int*)d_in[1];
    float* out = (float*)d_out;

    k1_gen<<<512, 256>>>(seed);           // 131072 independent (t, b) threads
    k2_chain<<<16, 576>>>();              // one block per batch: spec + prefix + replay
    dim3 grid(2, 4096);                   // 2*256 = 512 sixteen-wide threads per row
    k4_gather<<<grid, 256>>>(x, out);
}

// round 7
// speedup vs baseline: 1.2343x; 1.2343x over previous
#include <cuda_runtime.h>
#include <stdint.h>
#include <math.h>

#define T_LEN 8192
#define B_CNT 16
#define NSTEP 8189            // T-3 markov samples
#define SEG_N 64
#define SEG_L 128             // SEG_N*SEG_L = 8192 (pad last 3 steps)
#define SMP_STRIDE 8208       // 16-byte lead pad + 8192

// ---------------- device scratch (no allocations allowed) ----------------
__device__ uint8_t g_snsp[B_CNT * T_LEN];        // per (b,t): sn | sp<<2
__device__ uint8_t g_smp[B_CNT * SMP_STRIDE];    // [16B pad][8192 samples] per b
__device__ uint2   g_keys[T_LEN];                // keys[t] = tf(key, 0, t)

// ---------------- threefry-2x32 (20 rounds), matches JAX exactly ----------------
__device__ __forceinline__ void tf2x32(uint32_t k0, uint32_t k1,
                                       uint32_t x0, uint32_t x1,
                                       uint32_t& o0, uint32_t& o1) {
    uint32_t ks2 = k0 ^ k1 ^ 0x1BD11BDAu;
    x0 += k0; x1 += k1;
#define RND(r) { x0 += x1; x1 = __funnelshift_l(x1, x1, (r)); x1 ^= x0; }
    RND(13) RND(15) RND(26) RND(6)
    x0 += k1; x1 += ks2 + 1u;
    RND(17) RND(29) RND(16) RND(24)
    x0 += ks2; x1 += k0 + 2u;
    RND(13) RND(15) RND(26) RND(6)
    x0 += k0; x1 += k1 + 3u;
    RND(17) RND(29) RND(16) RND(24)
    x0 += k1; x1 += ks2 + 4u;
    RND(13) RND(15) RND(26) RND(6)
    x0 += ks2; x1 += k0 + 5u;
#undef RND
    o0 = x0; o1 = x1;
}

// JAX uniform(minval=tiny, maxval=1) from raw bits
__device__ __forceinline__ float u_from_bits(uint32_t bits) {
    const float tiny = 1.1754943508222875e-38f;  // FLT_MIN
    float f = __uint_as_float((bits >> 9) | 0x3f800000u) - 1.0f;
    return fmaxf(tiny, f + tiny);
}

__device__ __forceinline__ float gum_fast(uint32_t bits) {
    float u = u_from_bits(bits);
    return -logf(-logf(u));
}

// correctly-rounded f32 gumbel via double logs (only when argmax margin is tight)
__device__ __noinline__ float gum_precise(uint32_t bits) {
    float u = u_from_bits(bits);
    float inner = (float)log((double)u);
    return -(float)log((double)(-inner));
}

// ---------------- K0: per-step keys (partitionable split) ----------------
__global__ void k0_keys(const int* __restrict__ seed_ptr) {
    int t = blockIdx.x * blockDim.x + threadIdx.x;    // 8192 threads
    uint32_t a0, a1;
    tf2x32(0u, (uint32_t)(*seed_ptr), 0u, (uint32_t)t, a0, a1);
    g_keys[t] = make_uint2(a0, a1);
}

// ---------------- K1: per-(t,b) candidate samples sn / sp ----------------
// warp = 32 consecutive t, fixed b: coalesced key loads + coalesced byte stores.
__global__ void __launch_bounds__(256) k1_gen() {
    int tid = blockIdx.x * blockDim.x + threadIdx.x;   // 131072 threads
    int t = tid & (T_LEN - 1);
    int b = tid >> 13;

    if (t >= NSTEP) {     // pad steps 8189..8191 (never affect the output)
        g_snsp[b * T_LEN + t] = (uint8_t)(1u | (1u << 2));
        return;
    }

    uint2 kt = __ldg(&g_keys[t]);
    uint32_t kt0 = kt.x, kt1 = kt.y;

    uint32_t bt[3];
#pragma unroll
    for (int k = 0; k < 3; k++) {   // bits[(16,3)][3b+k] = o0^o1 of tf(key_t, 0, j)
        uint32_t o0, o1;
        tf2x32(kt0, kt1, 0u, (uint32_t)(3 * b + k), o0, o1);
        bt[k] = o0 ^ o1;
    }

    // logits as exact-to-f32 precomputed literals (same values the DP path derives)
    const float lp  = (float)-2.3025850780928845;   // ln(f32(0.1))
    const float ls  = (float)-0.22314353641304875;  // ln(f32(0.8))
    const float l21 = (float)-0.11778302820580285;  // ln(f32(s/(p+s)))
    const float l22 = (float)-2.19722456988563878;  // ln(f32(p/(p+s)))

    float g0 = gum_fast(bt[0]), g1 = gum_fast(bt[1]), g2 = gum_fast(bt[2]);
    float v0 = lp + g0, v1 = ls + g1, v2 = lp + g2;
    float w1 = l21 + g1, w2 = l22 + g2;

    float mmin = fminf(fminf(fabsf(v0 - v1), fabsf(v0 - v2)),
                       fminf(fabsf(v1 - v2), fabsf(w1 - w2)));
    if (mmin < 1e-3f) {   // tight argmax margin: redo exactly (DP logs, rare path)
        double p = 0.1, s = 1.0 - 2.0 * 0.1;
        float flp  = (float)log((double)(float)p);
        float fls  = (float)log((double)(float)s);
        float fl21 = (float)log((double)(float)(s / (p + s)));
        float fl22 = (float)log((double)(float)(p / (p + s)));
        g0 = gum_precise(bt[0]); g1 = gum_precise(bt[1]); g2 = gum_precise(bt[2]);
        v0 = flp + g0; v1 = fls + g1; v2 = flp + g2;
        w1 = fl21 + g1; w2 = fl22 + g2;
    }

    int sn = 0; float best = v0;              // jnp.argmax first-max semantics
    if (v1 > best) { best = v1; sn = 1; }
    if (v2 > best) { sn = 2; }
    int sp = (w1 >= w2) ? 1 : 2;              // special row [-inf, w1, w2]

    g_snsp[b * T_LEN + t] = (uint8_t)(sn | (sp << 2));
}

// compose two 9-state maps packed as nibbles: (f ∘ g)(i) = f[g[i]]
__device__ __forceinline__ unsigned long long map_comp(unsigned long long f,
                                                       unsigned long long g) {
    unsigned long long r = 0ull;
#pragma unroll
    for (int i = 0; i < 9; i++) {
        uint32_t gi = (uint32_t)(g >> (4 * i)) & 15u;
        uint32_t fi = (uint32_t)(f >> (4 * gi)) & 15u;
        r |= (unsigned long long)fi << (4 * i);
    }
    return r;
}

// ---------------- K2: fused speculative chain (one block per batch) ----------------
__global__ void __launch_bounds__(576) k2_chain() {
    __shared__ uint8_t s_end[SEG_N][9];
    __shared__ unsigned long long s_map[SEG_N];
    int b = blockIdx.x;
    int tid = threadIdx.x;

    {   // ---- phase A: 64 segs x 9 speculative start states ----
        int seg = tid / 9, s0 = tid % 9;
        const uint4* src = (const uint4*)(g_snsp + b * T_LEN + seg * SEG_L);
        uint4 w[8];
#pragma unroll
        for (int q = 0; q < 8; q++) w[q] = __ldg(&src[q]);   // MLP=8 up front
        uint32_t cc = (((uint32_t)(s0 / 3)) << 2) | (uint32_t)(s0 % 3);
#pragma unroll
        for (int q = 0; q < 8; q++) {
            uint32_t ws[4] = {w[q].x, w[q].y, w[q].z, w[q].w};
#pragma unroll
            for (int wi = 0; wi < 4; wi++) {
                uint32_t word = ws[wi];
#pragma unroll
                for (int bi = 0; bi < 4; bi++) {
                    uint32_t byte = word >> (8 * bi);
                    uint32_t s = (cc == 9u) ? ((byte >> 2) & 3u) : (byte & 3u);
                    cc = (s << 2) | (cc >> 2);
                }
            }
        }
        s_end[seg][s0] = (uint8_t)((cc >> 2) * 3u + (cc & 3u));
    }
    __syncthreads();

    if (tid < SEG_N) {    // pack 9 end states into one nibble map
        unsigned long long m = 0ull;
#pragma unroll
        for (int i = 0; i < 9; i++)
            m |= (unsigned long long)s_end[tid][i] << (4 * i);
        s_map[tid] = m;
    }
    __syncthreads();

    // ---- phase B: Kogge-Stone inclusive prefix s_map[i] = m_i ∘ ... ∘ m_0 ----
#pragma unroll
    for (int d = 1; d < SEG_N; d <<= 1) {
        unsigned long long v;
        if (tid < SEG_N) {
            v = s_map[tid];
            if (tid >= d) v = map_comp(v, s_map[tid - d]);
        }
        __syncthreads();
        if (tid < SEG_N) s_map[tid] = v;
        __syncthreads();
    }

    if (tid == 0) g_smp[b * SMP_STRIDE + 15] = 1;   // pad byte: m(to=0) = 1

    if (tid < SEG_N) {    // ---- phase C: replay with true start ----
        int seg = tid;
        int i0 = (seg == 0) ? 4 : (int)((s_map[seg - 1] >> 16) & 15ull);
        const uint4* src = (const uint4*)(g_snsp + b * T_LEN + seg * SEG_L);
        uint4 w[8];
#pragma unroll
        for (int q = 0; q < 8; q++) w[q] = __ldg(&src[q]);
        uint32_t cc = (((uint32_t)(i0 / 3)) << 2) | (uint32_t)(i0 % 3);
        uint4* dst = (uint4*)(g_smp + b * SMP_STRIDE + 16 + seg * SEG_L);
#pragma unroll
        for (int q = 0; q < 8; q++) {
            uint32_t in[4] = {w[q].x, w[q].y, w[q].z, w[q].w};
            uint32_t out[4];
#pragma unroll
            for (int wi = 0; wi < 4; wi++) {
                uint32_t word = in[wi], ow = 0u;
#pragma unroll
                for (int bi = 0; bi < 4; bi++) {
                    uint32_t s = (cc == 9u) ? ((word >> (8 * bi + 2)) & 3u)
                                            : ((word >> (8 * bi)) & 3u);
                    cc = (s << 2) | (cc >> 2);
                    ow |= s << (8 * bi);
                }
                out[wi] = ow;
            }
            dst[q] = make_uint4(out[0], out[1], out[2], out[3]);
        }
    }
}

// ---------------- K4: vectorized gather (8 outputs / thread) ----------------------
// out[bi, to] = x[bi, to + m(b,to)];  m bytes live at g_smp[b*STRIDE + 15 + to]
__global__ void k4_gather(const float* __restrict__ x, float* __restrict__ out) {
    int t8 = blockIdx.x * blockDim.x + threadIdx.x;  // oct index: outputs 8t8..8t8+7
    int bi = blockIdx.y;                             // b*256 + i
    int b = bi >> 8;

    const uint32_t* mw = (const uint32_t*)(g_smp + b * SMP_STRIDE);
    uint32_t u0 = __ldg(&mw[2 * t8 + 3]);
    uint32_t u1 = __ldg(&mw[2 * t8 + 4]);
    uint32_t u2 = __ldg(&mw[2 * t8 + 5]);
    uint32_t mlo = __funnelshift_r(u0, u1, 24);      // bytes: m0..m3
    uint32_t mhi = __funnelshift_r(u1, u2, 24);      // bytes: m4..m7

    const float* xr = x + (size_t)bi * 8192 + 8 * t8;
    float4 a  = *(const float4*)xr;                  // x[8t8 .. +3]
    float4 bb = *(const float4*)(xr + 4);            // x[8t8+4 .. +7]
    float e0 = 0.f, e1 = 0.f;
    bool full = (t8 < 1023);
    if (full) { float2 e = *(const float2*)(xr + 8); e0 = e.x; e1 = e.y; }

    uint32_t m0 = mlo & 3u, m1 = (mlo >> 8) & 3u, m2 = (mlo >> 16) & 3u, m3 = (mlo >> 24) & 3u;
    uint32_t m4 = mhi & 3u, m5 = (mhi >> 8) & 3u, m6 = (mhi >> 16) & 3u, m7 = (mhi >> 24) & 3u;

    float o0 = (m0 == 0u) ? a.x  : ((m0 == 1u) ? a.y  : a.z);
    float o1 = (m1 == 0u) ? a.y  : ((m1 == 1u) ? a.z  : a.w);
    float o2 = (m2 == 0u) ? a.z  : ((m2 == 1u) ? a.w  : bb.x);
    float o3 = (m3 == 0u) ? a.w  : ((m3 == 1u) ? bb.x : bb.y);
    float o4 = (m4 == 0u) ? bb.x : ((m4 == 1u) ? bb.y : bb.z);
    float o5 = (m5 == 0u) ? bb.y : ((m5 == 1u) ? bb.z : bb.w);
    float o6 = (m6 == 0u) ? bb.z : ((m6 == 1u) ? bb.w : e0);
    float o7 = (m7 == 0u) ? bb.w : ((m7 == 1u) ? e0   : e1);

    float* orow = out + (size_t)bi * 8190 + 8 * t8;
    bool al16 = ((bi & 1) == 0);                     // even rows: 16B-aligned stores
    if (full) {
        if (al16) {
            *(float4*)orow       = make_float4(o0, o1, o2, o3);
            *(float4*)(orow + 4) = make_float4(o4, o5, o6, o7);
        } else {
            float2* p = (float2*)orow;
            p[0] = make_float2(o0, o1); p[1] = make_float2(o2, o3);
            p[2] = make_float2(o4, o5); p[3] = make_float2(o6, o7);
        }
    } else {                                         // last oct: 6 outputs (8190 = 8*1023+6)
        if (al16) {
            *(float4*)orow = make_float4(o0, o1, o2, o3);
            *(float2*)(orow + 4) = make_float2(o4, o5);
        } else {
            float2* p = (float2*)orow;
            p[0] = make_float2(o0, o1); p[1] = make_float2(o2, o3);
            p[2] = make_float2(o4, o5);
        }
    }
}

extern "C" void kernel_launch(void* const* d_in, const int* in_sizes, int n_in,
                              void* d_out, int out_size) {
    const float* x = (const float*)d_in[0];
    const int* seed = (const int*)d_in[1];
    float* out = (float*)d_out;

    k0_keys<<<16, 512>>>(seed);           // 8192 step keys
    k1_gen<<<512, 256>>>();               // 131072 independent (t, b) threads
    k2_chain<<<16, 576>>>();              // one block per batch: spec + prefix + replay
    dim3 grid(4, 4096);                   // 4*256 = 1024 octs per row
    k4_gather<<<grid, 256>>>(x, out);
}

// round 8
// speedup vs baseline: 1.2459x; 1.0094x over previous
#include <cuda_runtime.h>
#include <stdint.h>
#include <math.h>

#define T_LEN 8192
#define B_CNT 16
#define NSTEP 8189            // T-3 markov samples
#define SEG_N 128
#define SEG_L 64              // SEG_N*SEG_L = 8192 (pad last 3 steps)
#define SMP_STRIDE 8208       // 16-byte lead pad + 8192
#define N_TRIPS (B_CNT * T_LEN)

// ---------------- device scratch (no allocations allowed) ----------------
__device__ uint8_t g_snsp[B_CNT * T_LEN];        // per (b,t): sn | sp<<2
__device__ uint8_t g_smp[B_CNT * SMP_STRIDE];    // [16B pad][8192 samples] per b
__device__ uint2   g_keys[T_LEN];                // keys[t] = tf(key, 0, t)

// ---------------- threefry-2x32 (20 rounds), matches JAX exactly ----------------
__device__ __forceinline__ void tf2x32(uint32_t k0, uint32_t k1,
                                       uint32_t x0, uint32_t x1,
                                       uint32_t& o0, uint32_t& o1) {
    uint32_t ks2 = k0 ^ k1 ^ 0x1BD11BDAu;
    x0 += k0; x1 += k1;
#define RND(r) { x0 += x1; x1 = __funnelshift_l(x1, x1, (r)); x1 ^= x0; }
    RND(13) RND(15) RND(26) RND(6)
    x0 += k1; x1 += ks2 + 1u;
    RND(17) RND(29) RND(16) RND(24)
    x0 += ks2; x1 += k0 + 2u;
    RND(13) RND(15) RND(26) RND(6)
    x0 += k0; x1 += k1 + 3u;
    RND(17) RND(29) RND(16) RND(24)
    x0 += k1; x1 += ks2 + 4u;
    RND(13) RND(15) RND(26) RND(6)
    x0 += ks2; x1 += k0 + 5u;
#undef RND
    o0 = x0; o1 = x1;
}

// JAX uniform(minval=tiny, maxval=1) from raw bits
__device__ __forceinline__ float u_from_bits(uint32_t bits) {
    const float tiny = 1.1754943508222875e-38f;  // FLT_MIN
    float f = __uint_as_float((bits >> 9) | 0x3f800000u) - 1.0f;
    return fmaxf(tiny, f + tiny);
}

__device__ __forceinline__ float gum_fast(uint32_t bits) {
    float u = u_from_bits(bits);
    return -logf(-logf(u));
}

// correctly-rounded f32 gumbel via double logs (only when argmax margin is tight)
__device__ __noinline__ float gum_precise(uint32_t bits) {
    float u = u_from_bits(bits);
    float inner = (float)log((double)u);
    return -(float)log((double)(-inner));
}

// ---------------- K0: per-step keys (partitionable split) ----------------
__global__ void k0_keys(const int* __restrict__ seed_ptr) {
    int t = blockIdx.x * blockDim.x + threadIdx.x;    // 8192 threads
    uint32_t a0, a1;
    tf2x32(0u, (uint32_t)(*seed_ptr), 0u, (uint32_t)t, a0, a1);
    g_keys[t] = make_uint2(a0, a1);
}

// ---------------- K1: lane-triple sampler ----------------
// 3 lanes per (t,b): each computes ONE threefry + gumbel; base lane combines
// via shuffles and stores the decision byte. 10 trips per warp (lanes 30,31 idle).
__global__ void __launch_bounds__(256) k1_gen() {
    int warp_g = (blockIdx.x * blockDim.x + threadIdx.x) >> 5;
    int lane = threadIdx.x & 31;
    int trio = lane / 3;                 // 0..10 (10 => idle lanes 30,31)
    int k = lane - trio * 3;
    int trip = warp_g * 10 + trio;
    bool active = (lane < 30) && (trip < N_TRIPS);
    int t = trip & (T_LEN - 1);
    int b = trip >> 13;

    // logits as exact-to-f32 precomputed literals (same values the DP path derives)
    const float lp  = (float)-2.3025850780928845;   // ln(f32(0.1))
    const float ls  = (float)-0.22314353641304875;  // ln(f32(0.8))
    const float l21 = (float)-0.11778302820580285;  // ln(f32(s/(p+s)))
    const float l22 = (float)-2.19722456988563878;  // ln(f32(p/(p+s)))

    uint32_t bt = 0u;
    float vn = -3e38f, vs = -3e38f;
    if (active && t < NSTEP) {
        uint2 kt = __ldg(&g_keys[t]);
        uint32_t o0, o1;
        tf2x32(kt.x, kt.y, 0u, (uint32_t)(3 * b + k), o0, o1);
        bt = o0 ^ o1;
        float g = gum_fast(bt);
        vn = ((k == 1) ? ls : lp) + g;                       // normal row [p, s, p]
        vs = (k == 1) ? (l21 + g) : ((k == 2) ? (l22 + g) : -3e38f);  // special row
    }

    // gather triple results to the base lane (k==0)
    unsigned mask = 0xFFFFFFFFu;
    int s1 = trio * 3 + 1; if (s1 > 31) s1 = 31;
    int s2 = trio * 3 + 2; if (s2 > 31) s2 = 31;
    float vn1 = __shfl_sync(mask, vn, s1);
    float vn2 = __shfl_sync(mask, vn, s2);
    float w1  = __shfl_sync(mask, vs, s1);
    float w2  = __shfl_sync(mask, vs, s2);
    uint32_t bt1 = __shfl_sync(mask, bt, s1);
    uint32_t bt2 = __shfl_sync(mask, bt, s2);

    if (k == 0 && active) {
        if (t >= NSTEP) {   // pad steps 8189..8191 (never affect the output)
            g_snsp[b * T_LEN + t] = (uint8_t)(1u | (1u << 2));
            return;
        }
        float v0 = vn, v1 = vn1, v2 = vn2;

        float mmin = fminf(fminf(fabsf(v0 - v1), fabsf(v0 - v2)),
                           fminf(fabsf(v1 - v2), fabsf(w1 - w2)));
        if (mmin < 1e-3f) {  // tight argmax margin: redo exactly (DP logs, rare)
            double p = 0.1, s = 1.0 - 2.0 * 0.1;
            float flp  = (float)log((double)(float)p);
            float fls  = (float)log((double)(float)s);
            float fl21 = (float)log((double)(float)(s / (p + s)));
            float fl22 = (float)log((double)(float)(p / (p + s)));
            float g0 = gum_precise(bt), g1 = gum_precise(bt1), g2 = gum_precise(bt2);
            v0 = flp + g0; v1 = fls + g1; v2 = flp + g2;
            w1 = fl21 + g1; w2 = fl22 + g2;
        }

        int sn = 0; float best = v0;          // jnp.argmax first-max semantics
        if (v1 > best) { best = v1; sn = 1; }
        if (v2 > best) { sn = 2; }
        int sp = (w1 >= w2) ? 1 : 2;          // special row [-inf, w1, w2]

        g_snsp[b * T_LEN + t] = (uint8_t)(sn | (sp << 2));
    }
}

// compose two 9-state maps packed as nibbles: (f ∘ g)(i) = f[g[i]]
__device__ __forceinline__ unsigned long long map_comp(unsigned long long f,
                                                       unsigned long long g) {
    unsigned long long r = 0ull;
#pragma unroll
    for (int i = 0; i < 9; i++) {
        uint32_t gi = (uint32_t)(g >> (4 * i)) & 15u;
        uint32_t fi = (uint32_t)(f >> (4 * gi)) & 15u;
        r |= (unsigned long long)fi << (4 * i);
    }
    return r;
}

// run one speculative 64-step chain over 4 words; returns end state (cc form)
__device__ __forceinline__ uint32_t run_seg(const uint4 w[4], uint32_t cc) {
#pragma unroll
    for (int q = 0; q < 4; q++) {
        uint32_t ws[4] = {w[q].x, w[q].y, w[q].z, w[q].w};
#pragma unroll
        for (int wi = 0; wi < 4; wi++) {
            uint32_t word = ws[wi];
#pragma unroll
            for (int bi = 0; bi < 4; bi++) {
                uint32_t byte = word >> (8 * bi);
                uint32_t s = (cc == 9u) ? ((byte >> 2) & 3u) : (byte & 3u);
                cc = (s << 2) | (cc >> 2);
            }
        }
    }
    return cc;
}

// ---------------- K2: fused speculative chain (one block per batch) ----------------
// 128 segs x 64 steps. phase A: 576 threads x 2 items (ILP-2 chains);
// phase B: 7-round Kogge-Stone prefix; phase C: 64-step replay.
__global__ void __launch_bounds__(576) k2_chain() {
    __shared__ uint8_t s_end[SEG_N][9];
    __shared__ unsigned long long s_map[SEG_N];
    int b = blockIdx.x;
    int tid = threadIdx.x;

    {   // ---- phase A: items tid and tid+576 of 1152 (seg, s0) pairs ----
        int segA = tid / 9, sA = tid % 9;
        int itemB = tid + 576;
        int segB = itemB / 9, sB = itemB % 9;
        const uint4* srcA = (const uint4*)(g_snsp + b * T_LEN + segA * SEG_L);
        const uint4* srcB = (const uint4*)(g_snsp + b * T_LEN + segB * SEG_L);
        uint4 wA[4], wB[4];
#pragma unroll
        for (int q = 0; q < 4; q++) { wA[q] = __ldg(&srcA[q]); wB[q] = __ldg(&srcB[q]); }
        uint32_t ccA = run_seg(wA, (((uint32_t)(sA / 3)) << 2) | (uint32_t)(sA % 3));
        uint32_t ccB = run_seg(wB, (((uint32_t)(sB / 3)) << 2) | (uint32_t)(sB % 3));
        s_end[segA][sA] = (uint8_t)((ccA >> 2) * 3u + (ccA & 3u));
        s_end[segB][sB] = (uint8_t)((ccB >> 2) * 3u + (ccB & 3u));
    }
    __syncthreads();

    if (tid < SEG_N) {    // pack 9 end states into one nibble map
        unsigned long long m = 0ull;
#pragma unroll
        for (int i = 0; i < 9; i++)
            m |= (unsigned long long)s_end[tid][i] << (4 * i);
        s_map[tid] = m;
    }
    __syncthreads();

    // ---- phase B: Kogge-Stone inclusive prefix s_map[i] = m_i ∘ ... ∘ m_0 ----
#pragma unroll
    for (int d = 1; d < SEG_N; d <<= 1) {
        unsigned long long v;
        if (tid < SEG_N) {
            v = s_map[tid];
            if (tid >= d) v = map_comp(v, s_map[tid - d]);
        }
        __syncthreads();
        if (tid < SEG_N) s_map[tid] = v;
        __syncthreads();
    }

    if (tid == 0) g_smp[b * SMP_STRIDE + 15] = 1;   // pad byte: m(to=0) = 1

    if (tid < SEG_N) {    // ---- phase C: replay with true start ----
        int seg = tid;
        int i0 = (seg == 0) ? 4 : (int)((s_map[seg - 1] >> 16) & 15ull);
        const uint4* src = (const uint4*)(g_snsp + b * T_LEN + seg * SEG_L);
        uint4 w[4];
#pragma unroll
        for (int q = 0; q < 4; q++) w[q] = __ldg(&src[q]);
        uint32_t cc = (((uint32_t)(i0 / 3)) << 2) | (uint32_t)(i0 % 3);
        uint4* dst = (uint4*)(g_smp + b * SMP_STRIDE + 16 + seg * SEG_L);
#pragma unroll
        for (int q = 0; q < 4; q++) {
            uint32_t in[4] = {w[q].x, w[q].y, w[q].z, w[q].w};
            uint32_t out[4];
#pragma unroll
            for (int wi = 0; wi < 4; wi++) {
                uint32_t word = in[wi], ow = 0u;
#pragma unroll
                for (int bi = 0; bi < 4; bi++) {
                    uint32_t s = (cc == 9u) ? ((word >> (8 * bi + 2)) & 3u)
                                            : ((word >> (8 * bi)) & 3u);
                    cc = (s << 2) | (cc >> 2);
                    ow |= s << (8 * bi);
                }
                out[wi] = ow;
            }
            dst[q] = make_uint4(out[0], out[1], out[2], out[3]);
        }
    }
}

// ---------------- K4: vectorized gather (4 outputs / thread; round-3 form) --------
// out[bi, to] = x[bi, to + m(b,to)];  m bytes live at g_smp[b*STRIDE + 15 + to]
__global__ void k4_gather(const float* __restrict__ x, float* __restrict__ out) {
    int t = blockIdx.x * blockDim.x + threadIdx.x;   // quad index: outputs 4t..4t+3
    int bi = blockIdx.y;                             // b*256 + i
    int b = bi >> 8;

    // m bytes for j=0..3 are at byte positions 4t+15 .. 4t+18 -> words t+3, t+4
    const uint32_t* mw = (const uint32_t*)(g_smp + b * SMP_STRIDE);
    uint32_t w0 = __ldg(&mw[t + 3]);
    uint32_t w1 = __ldg(&mw[t + 4]);
    uint32_t mword = __funnelshift_r(w0, w1, 24);    // byte j = m for output 4t+j

    const float* xr = x + (size_t)bi * 8192 + 4 * t;
    float4 v = *(const float4*)xr;                   // 16B aligned
    float v4 = 0.f, v5 = 0.f;
    bool full = (t < 2047);
    if (full) { float2 ex = *(const float2*)(xr + 4); v4 = ex.x; v5 = ex.y; }

    uint32_t m0 = mword & 3u, m1 = (mword >> 8) & 3u,
             m2 = (mword >> 16) & 3u, m3 = (mword >> 24) & 3u;
    float o0 = (m0 == 0u) ? v.x : ((m0 == 1u) ? v.y : v.z);
    float o1 = (m1 == 0u) ? v.y : ((m1 == 1u) ? v.z : v.w);
    float o2 = (m2 == 0u) ? v.z : ((m2 == 1u) ? v.w : v4);
    float o3 = (m3 == 0u) ? v.w : ((m3 == 1u) ? v4 : v5);

    float2* orow = (float2*)(out + (size_t)bi * 8190 + 4 * t);  // 8B aligned
    orow[0] = make_float2(o0, o1);
    if (full) orow[1] = make_float2(o2, o3);
}

extern "C" void kernel_launch(void* const* d_in, const int* in_sizes, int n_in,
                              void* d_out, int out_size) {
    const float* x = (const float*)d_in[0];
    const int* seed = (const int*)d_in[1];
    float* out = (float*)d_out;

    k0_keys<<<16, 512>>>(seed);           // 8192 step keys
    int warps = (N_TRIPS + 9) / 10;       // 10 trips per warp
    int blocks = (warps + 7) / 8;         // 8 warps per block
    k1_gen<<<blocks, 256>>>();            // lane-triple sampler
    k2_chain<<<16, 576>>>();              // one block per batch: spec + prefix + replay
    dim3 grid(8, 4096);                   // 8*256 = 2048 quads per row
    k4_gather<<<grid, 256>>>(x, out);
}